// round 12
// baseline (speedup 1.0000x reference)
#include <cuda_runtime.h>
#include <cuda_bf16.h>
#include <math.h>
#include <cstdint>

#define B_SZ 512
#define K_SZ 32
#define D_SZ 768
#define N_SENSES 200000
#define NEG_INF -1e30f

#define WARPS_PER_CTA 4
#define CTA_THREADS (WARPS_PER_CTA * 32)   // 128
#define ITEMS_PER_WARP (K_SZ / WARPS_PER_CTA)  // 8 candidates per warp
#define BURST 4                            // rows per load burst
#define GRID_CTAS B_SZ                     // one sample per CTA -> 512 CTAs

// Global scratch. Counters use atomicInc wrap -> self-reset each full launch,
// deterministic under graph replay.
__device__ float    g_logits[B_SZ * K_SZ];
__device__ float    g_nll[B_SZ];
__device__ unsigned g_cnt[B_SZ];     // wraps at WARPS_PER_CTA-1 (4 warp arrivals)
__device__ unsigned g_done = 0;      // wraps at B_SZ-1

__global__ __launch_bounds__(CTA_THREADS, 4)
void cbert_burst4_kernel(const float* __restrict__ reps,
                         const float* __restrict__ weight,
                         const float* __restrict__ bias,
                         const int* __restrict__ sense_ids,
                         const int* __restrict__ target_ids,
                         float* __restrict__ out, int out_size) {
    __shared__ __align__(16) float s_reps[D_SZ];   // 3 KB

    const int lane = threadIdx.x & 31;
    const int warp = threadIdx.x >> 5;
    const int b  = blockIdx.x;                     // sample
    const int k0 = warp * ITEMS_PER_WARP;          // first candidate of this warp

    // Stage reps[b] into smem (192 float4 over 128 threads).
    {
        const float4* src = reinterpret_cast<const float4*>(reps + (size_t)b * D_SZ);
        float4* dst = reinterpret_cast<float4*>(s_reps);
        #pragma unroll
        for (int i = threadIdx.x; i < D_SZ / 4; i += CTA_THREADS)
            dst[i] = src[i];
    }

    // Warp-uniform candidate ids (two 16B loads).
    int ids[ITEMS_PER_WARP];
    {
        const int4* ip = reinterpret_cast<const int4*>(&sense_ids[b * K_SZ + k0]);
        int4 a = __ldg(&ip[0]);
        int4 c = __ldg(&ip[1]);
        ids[0] = a.x; ids[1] = a.y; ids[2] = a.z; ids[3] = a.w;
        ids[4] = c.x; ids[5] = c.y; ids[6] = c.z; ids[7] = c.w;
    }

    __syncthreads();   // s_reps ready
    const float4* r4 = reinterpret_cast<const float4*>(s_reps);

    // Two bursts of 4 rows: 24 front-batched LDG.128 per burst (12 KB in flight).
    #pragma unroll
    for (int t = 0; t < ITEMS_PER_WARP / BURST; ++t) {
        int  idr[BURST];
        bool vr[BURST];
        const float4* wp[BURST];
        #pragma unroll
        for (int rr = 0; rr < BURST; ++rr) {
            idr[rr] = ids[t * BURST + rr];
            vr[rr]  = (idr[rr] >= 0 && idr[rr] < N_SENSES);
            wp[rr]  = reinterpret_cast<const float4*>(
                          weight + (size_t)(vr[rr] ? idr[rr] : 0) * D_SZ);
        }

        float4 buf[BURST][6];
        #pragma unroll
        for (int j = 0; j < 6; ++j)
            #pragma unroll
            for (int rr = 0; rr < BURST; ++rr)
                if (vr[rr]) buf[rr][j] = wp[rr][lane + 32 * j];

        float bs[BURST];
        #pragma unroll
        for (int rr = 0; rr < BURST; ++rr)
            bs[rr] = vr[rr] ? __ldg(&bias[idr[rr]]) : 0.f;

        float acc[BURST] = {0.f, 0.f, 0.f, 0.f};
        #pragma unroll
        for (int j = 0; j < 6; ++j) {
            const float4 r = r4[lane + 32 * j];    // one LDS.128, reused 4x
            #pragma unroll
            for (int rr = 0; rr < BURST; ++rr) {
                if (vr[rr]) {
                    acc[rr] = fmaf(buf[rr][j].x, r.x, acc[rr]);
                    acc[rr] = fmaf(buf[rr][j].y, r.y, acc[rr]);
                    acc[rr] = fmaf(buf[rr][j].z, r.z, acc[rr]);
                    acc[rr] = fmaf(buf[rr][j].w, r.w, acc[rr]);
                }
            }
        }
        #pragma unroll
        for (int off = 16; off > 0; off >>= 1)
            #pragma unroll
            for (int rr = 0; rr < BURST; ++rr)
                acc[rr] += __shfl_down_sync(0xFFFFFFFFu, acc[rr], off);

        if (lane == 0) {
            float4 lg;
            lg.x = vr[0] ? acc[0] + bs[0] : NEG_INF;
            lg.y = vr[1] ? acc[1] + bs[1] : NEG_INF;
            lg.z = vr[2] ? acc[2] + bs[2] : NEG_INF;
            lg.w = vr[3] ? acc[3] + bs[3] : NEG_INF;
            __stcg(reinterpret_cast<float4*>(&g_logits[b * K_SZ + k0 + t * BURST]), lg);
        }
    }

    // ---- Count warp arrivals for sample b ----
    unsigned old = 0;
    if (lane == 0) {
        __threadfence();
        old = atomicInc(&g_cnt[b], WARPS_PER_CTA - 1);   // wraps after 4
    }
    old = __shfl_sync(0xFFFFFFFFu, old, 0);
    if (old != WARPS_PER_CTA - 1) return;

    // ---- Phase 2: last warp of sample b -> 32-wide masked softmax ----
    __threadfence();
    float v = __ldcg(&g_logits[b * K_SZ + lane]);

    float mval = v; int midx = lane;
    #pragma unroll
    for (int off = 16; off > 0; off >>= 1) {
        float ov = __shfl_down_sync(0xFFFFFFFFu, mval, off);
        int   oi = __shfl_down_sync(0xFFFFFFFFu, midx, off);
        if (ov > mval || (ov == mval && oi < midx)) { mval = ov; midx = oi; }
    }
    mval = __shfl_sync(0xFFFFFFFFu, mval, 0);
    midx = __shfl_sync(0xFFFFFFFFu, midx, 0);

    float e = expf(v - mval);
    #pragma unroll
    for (int off = 16; off > 0; off >>= 1)
        e += __shfl_down_sync(0xFFFFFFFFu, e, off);
    float sumexp = __shfl_sync(0xFFFFFFFFu, e, 0);

    const int tgt = target_ids[b];
    float tlogit = __shfl_sync(0xFFFFFFFFu, v, tgt & 31);

    unsigned done2 = 0;
    if (lane == 0) {
        float nll = -(tlogit - mval - logf(sumexp));
        __stcg(&g_nll[b], nll);
        if (1 + b < out_size) out[1 + b] = (midx == tgt) ? 1.0f : 0.0f;
        __threadfence();
        done2 = atomicInc(&g_done, B_SZ - 1);            // wraps after 512
    }
    done2 = __shfl_sync(0xFFFFFFFFu, done2, 0);
    if (done2 != B_SZ - 1) return;

    // ---- Phase 3: deterministic fixed-order mean of 512 NLLs ----
    __threadfence();
    float acc = 0.f;
    #pragma unroll
    for (int i = 0; i < B_SZ / 32; ++i)
        acc += __ldcg(&g_nll[lane + 32 * i]);
    #pragma unroll
    for (int off = 16; off > 0; off >>= 1)
        acc += __shfl_down_sync(0xFFFFFFFFu, acc, off);
    if (lane == 0 && out_size > 0) out[0] = acc / (float)B_SZ;
}

extern "C" void kernel_launch(void* const* d_in, const int* in_sizes, int n_in,
                              void* d_out, int out_size) {
    const float* reps = (const float*)d_in[0];
    const float* weight = (const float*)d_in[1];
    const float* bias = (const float*)d_in[2];
    const int* sense_ids = (const int*)d_in[3];
    const int* target_ids = (const int*)d_in[4];
    float* out = (float*)d_out;

    cbert_burst4_kernel<<<GRID_CTAS, CTA_THREADS>>>(reps, weight, bias,
                                                    sense_ids, target_ids,
                                                    out, out_size);
}